// round 14
// baseline (speedup 1.0000x reference)
#include <cuda_runtime.h>
#include <cuda.h>
#include <cuda_bf16.h>
#include <cstdint>

// EWRLS level filter, algebraically reduced:
//   lam = clip(sigmoid(logit_lambda[c]), 1e-4, 1-1e-4)
//   S_t = lam*S_{t-1} + x_t ; Q_t = lam*Q_{t-1} + 1 ; y_t = S_t/Q_t
//
// R14: R12 single-producer warp-specialized pipeline, with (a) producer
// reordered load-first so read requests always lead write work, and
// (b) XSTG=4 read ring (96KB smem total, still 2 blocks/SM).

#define B_DIM 64
#define T_DIM 1024
#define C_DIM 512

#define CT      128              // consumer channels per block
#define TT      32               // timesteps per stage
#define XSTG    4
#define YSTG    2
#define NSTG    (T_DIM / TT)     // 32
#define STG_BYTES (TT * CT * 4)  // 16384
#define NBARS   (2 * XSTG + 2 * YSTG)
#define SMEM_BYTES ((XSTG + YSTG) * STG_BYTES + NBARS * 8)

// ---------------- device helpers ----------------
__device__ __forceinline__ uint32_t smem_u32(const void* p) {
    uint32_t a;
    asm("{ .reg .u64 t; cvta.to.shared.u64 t, %1; cvt.u32.u64 %0, t; }"
        : "=r"(a) : "l"(p));
    return a;
}
__device__ __forceinline__ void mbar_init(uint32_t mbar, uint32_t count) {
    asm volatile("mbarrier.init.shared.b64 [%0], %1;" :: "r"(mbar), "r"(count) : "memory");
}
__device__ __forceinline__ void mbar_expect_tx(uint32_t mbar, uint32_t bytes) {
    asm volatile("mbarrier.arrive.expect_tx.shared.b64 _, [%0], %1;"
                 :: "r"(mbar), "r"(bytes) : "memory");
}
__device__ __forceinline__ void mbar_arrive(uint32_t mbar) {
    asm volatile("mbarrier.arrive.shared.b64 _, [%0];" :: "r"(mbar) : "memory");
}
__device__ __forceinline__ void mbar_wait(uint32_t mbar, uint32_t phase) {
    uint32_t done;
    asm volatile(
        "{\n\t.reg .pred p;\n\t"
        "mbarrier.try_wait.parity.acquire.cta.shared::cta.b64 p, [%1], %2;\n\t"
        "selp.b32 %0, 1, 0, p;\n\t}"
        : "=r"(done) : "r"(mbar), "r"(phase) : "memory");
    if (!done) {
        asm volatile(
            "{\n\t.reg .pred P1;\n\t"
            "W_%=:\n\t"
            "mbarrier.try_wait.parity.acquire.cta.shared::cta.b64 P1, [%0], %1, 0x989680;\n\t"
            "@P1 bra.uni D_%=;\n\t"
            "bra.uni W_%=;\n\t"
            "D_%=:\n\t}"
            :: "r"(mbar), "r"(phase) : "memory");
    }
}
__device__ __forceinline__ void tma_load_2d(uint32_t dst, const CUtensorMap* m,
                                            int cx, int cy, uint32_t mbar) {
    asm volatile(
        "cp.async.bulk.tensor.2d.shared::cta.global.tile.mbarrier::complete_tx::bytes "
        "[%0], [%1, {%2, %3}], [%4];"
        :: "r"(dst), "l"(m), "r"(cx), "r"(cy), "r"(mbar) : "memory");
}
__device__ __forceinline__ void tma_store_2d(const CUtensorMap* m, int cx, int cy,
                                             uint32_t src) {
    asm volatile(
        "cp.async.bulk.tensor.2d.global.shared::cta.tile.bulk_group "
        "[%0, {%1, %2}], [%3];"
        :: "l"(m), "r"(cx), "r"(cy), "r"(src) : "memory");
}
__device__ __forceinline__ void tma_commit() {
    asm volatile("cp.async.bulk.commit_group;" ::: "memory");
}
template <int N>
__device__ __forceinline__ void tma_wait_group() {
    asm volatile("cp.async.bulk.wait_group %0;" :: "n"(N) : "memory");
}
__device__ __forceinline__ void fence_async_shared() {
    asm volatile("fence.proxy.async.shared::cta;" ::: "memory");
}

// ---------------- kernel ----------------
__global__ __launch_bounds__(160, 2)
void ewrls_ws_kernel(const __grid_constant__ CUtensorMap tmx,
                     const __grid_constant__ CUtensorMap tmy,
                     const float* __restrict__ logit_lambda) {
    extern __shared__ char smem[];
    float* xs = (float*)smem;                                  // [XSTG][TT][CT]
    float* ys = (float*)(smem + XSTG * STG_BYTES);             // [YSTG][TT][CT]
    uint64_t* bars = (uint64_t*)(smem + (XSTG + YSTG) * STG_BYTES);

    const int tid   = threadIdx.x;
    const int b     = blockIdx.x >> 2;
    const int ctile = blockIdx.x & 3;
    const int cx    = ctile * CT;
    const int cy0   = b * T_DIM;

    const uint32_t mb  = smem_u32(bars);
    const uint32_t xs0 = smem_u32(xs);
    const uint32_t ys0 = smem_u32(ys);

    auto XFULL  = [&](int i) { return mb + i * 8; };
    auto XEMPTY = [&](int i) { return mb + (XSTG + i) * 8; };
    auto YREADY = [&](int i) { return mb + (2 * XSTG + i) * 8; };
    auto YFREE  = [&](int i) { return mb + (2 * XSTG + YSTG + i) * 8; };

    if (tid == 0) {
#pragma unroll
        for (int i = 0; i < XSTG; i++) { mbar_init(XFULL(i), 1); mbar_init(XEMPTY(i), CT); }
#pragma unroll
        for (int i = 0; i < YSTG; i++) { mbar_init(YREADY(i), CT); mbar_init(YFREE(i), 1); }
    }
    __syncthreads();   // only block-wide barrier in the kernel

    if (tid >= CT) {
        // ---------------- producer (warp 4, lane 0) ----------------
        if (tid != CT) return;

        // prologue: XSTG loads in flight
#pragma unroll
        for (int s = 0; s < XSTG; s++) {
            mbar_expect_tx(XFULL(s), STG_BYTES);
            tma_load_2d(xs0 + s * STG_BYTES, &tmx, cx, cy0 + s * TT, XFULL(s));
        }

#pragma unroll 1
        for (int s = 0; s < NSTG; s++) {
            // (1) LOAD FIRST: consumers arrive XEMPTY(s%XSTG) before YREADY(s),
            // so the read for stage s+XSTG leaves before any store work below.
            if (s + XSTG < NSTG) {
                const int xb = s % XSTG, xr = s / XSTG;
                mbar_wait(XEMPTY(xb), (uint32_t)(xr & 1));
                mbar_expect_tx(XFULL(xb), STG_BYTES);
                tma_load_2d(xs0 + xb * STG_BYTES, &tmx,
                            cx, cy0 + (s + XSTG) * TT, XFULL(xb));
            }

            // (2) then the store for stage s
            const int yb = s % YSTG, yr = s / YSTG;
            mbar_wait(YREADY(yb), (uint32_t)(yr & 1));
            fence_async_shared();
            tma_store_2d(&tmy, cx, cy0 + s * TT, ys0 + yb * STG_BYTES);
            tma_commit();
            tma_wait_group<YSTG - 1>();    // store s-(YSTG-1) retired
            if (s >= YSTG - 1)
                mbar_arrive(YFREE((s - (YSTG - 1)) % YSTG));
        }
        tma_wait_group<0>();
        return;
    }

    // ---------------- consumers (tid 0..127) ----------------
    const int c = ctile * CT + tid;
    float l   = __ldg(&logit_lambda[c]);
    float lam = 1.0f / (1.0f + __expf(-l));
    lam = fminf(fmaxf(lam, 1e-4f), 1.0f - 1e-4f);

    float S = 0.0f, Q = 0.0f;

#pragma unroll 1
    for (int s = 0; s < NSTG; s++) {
        const int xb = s % XSTG, xr = s / XSTG;
        const int yb = s % YSTG, yr = s / YSTG;

        mbar_wait(XFULL(xb), (uint32_t)(xr & 1));           // x data landed
        if (s >= YSTG)
            mbar_wait(YFREE(yb), (uint32_t)((yr - 1) & 1)); // ys[yb] store retired

        const float* __restrict__ sb = xs + xb * (TT * CT) + tid;
        float*       __restrict__ db = ys + yb * (TT * CT) + tid;
#pragma unroll
        for (int g = 0; g < TT / 8; g++) {
            float xv[8];
#pragma unroll
            for (int u = 0; u < 8; u++) xv[u] = sb[(g * 8 + u) * CT];
#pragma unroll
            for (int u = 0; u < 8; u++) {
                S = fmaf(lam, S, xv[u]);
                Q = fmaf(lam, Q, 1.0f);
                db[(g * 8 + u) * CT] = __fdividef(S, Q);
            }
        }

        mbar_arrive(XEMPTY(xb));   // done reading xs[xb] (signalled BEFORE yready)
        mbar_arrive(YREADY(yb));   // ys[yb] fully written
    }
}

// ---------------- host ----------------
typedef CUresult (*EncodeTiledFn)(
    CUtensorMap*, CUtensorMapDataType, cuuint32_t, void*,
    const cuuint64_t*, const cuuint64_t*, const cuuint32_t*, const cuuint32_t*,
    CUtensorMapInterleave, CUtensorMapSwizzle, CUtensorMapL2promotion,
    CUtensorMapFloatOOBfill);

static EncodeTiledFn get_encode_fn() {
    static EncodeTiledFn fn = nullptr;
    if (!fn) {
        cudaDriverEntryPointQueryResult qr;
#if CUDART_VERSION >= 12050
        cudaGetDriverEntryPointByVersion("cuTensorMapEncodeTiled", (void**)&fn,
                                         12000, cudaEnableDefault, &qr);
#else
        cudaGetDriverEntryPoint("cuTensorMapEncodeTiled", (void**)&fn,
                                cudaEnableDefault, &qr);
#endif
    }
    return fn;
}

static void make_map(CUtensorMap* m, void* base) {
    cuuint64_t dims[2]    = {C_DIM, (cuuint64_t)B_DIM * T_DIM};
    cuuint64_t strides[1] = {C_DIM * sizeof(float)};
    cuuint32_t box[2]     = {CT, TT};
    cuuint32_t es[2]      = {1, 1};
    get_encode_fn()(m, CU_TENSOR_MAP_DATA_TYPE_FLOAT32, 2, base,
                    dims, strides, box, es,
                    CU_TENSOR_MAP_INTERLEAVE_NONE, CU_TENSOR_MAP_SWIZZLE_NONE,
                    CU_TENSOR_MAP_L2_PROMOTION_L2_128B,
                    CU_TENSOR_MAP_FLOAT_OOB_FILL_NONE);
}

extern "C" void kernel_launch(void* const* d_in, const int* in_sizes, int n_in,
                              void* d_out, int out_size) {
    const float* x;
    const float* logit_lambda;
    if (in_sizes[0] > in_sizes[1]) {
        x = (const float*)d_in[0];
        logit_lambda = (const float*)d_in[1];
    } else {
        x = (const float*)d_in[1];
        logit_lambda = (const float*)d_in[0];
    }
    float* y = (float*)d_out;

    CUtensorMap tmx, tmy;
    make_map(&tmx, (void*)x);
    make_map(&tmy, (void*)y);

    cudaFuncSetAttribute(ewrls_ws_kernel,
                         cudaFuncAttributeMaxDynamicSharedMemorySize, SMEM_BYTES);

    const int blocks = B_DIM * (C_DIM / CT);   // 256
    ewrls_ws_kernel<<<blocks, 160, SMEM_BYTES>>>(tmx, tmy, logit_lambda);
}

// round 15
// speedup vs baseline: 1.0434x; 1.0434x over previous
#include <cuda_runtime.h>
#include <cuda.h>
#include <cuda_bf16.h>
#include <cstdint>

// EWRLS level filter, algebraically reduced:
//   lam = clip(sigmoid(logit_lambda[c]), 1e-4, 1-1e-4)
//   S_t = lam*S_{t-1} + x_t ; Q_t = lam*Q_{t-1} + 1 ; y_t = S_t/Q_t
//
// R15: exact R12 champion structure (single-producer warp-specialized TMA
// pipeline, TT=32, XSTG=3, YSTG=2, 2 blocks/SM) with consumer mbarrier
// arrives reduced from per-thread (128) to per-warp (4) via __syncwarp +
// lane-0 arrive.

#define B_DIM 64
#define T_DIM 1024
#define C_DIM 512

#define CT      128              // consumer channels per block
#define TT      32               // timesteps per stage
#define XSTG    3
#define YSTG    2
#define NSTG    (T_DIM / TT)     // 32
#define STG_BYTES (TT * CT * 4)  // 16384
#define NBARS   (2 * XSTG + 2 * YSTG)           // 10
#define SMEM_BYTES ((XSTG + YSTG) * STG_BYTES + NBARS * 8)
#define NCW     (CT / 32)        // 4 consumer warps

// ---------------- device helpers ----------------
__device__ __forceinline__ uint32_t smem_u32(const void* p) {
    uint32_t a;
    asm("{ .reg .u64 t; cvta.to.shared.u64 t, %1; cvt.u32.u64 %0, t; }"
        : "=r"(a) : "l"(p));
    return a;
}
__device__ __forceinline__ void mbar_init(uint32_t mbar, uint32_t count) {
    asm volatile("mbarrier.init.shared.b64 [%0], %1;" :: "r"(mbar), "r"(count) : "memory");
}
__device__ __forceinline__ void mbar_expect_tx(uint32_t mbar, uint32_t bytes) {
    asm volatile("mbarrier.arrive.expect_tx.shared.b64 _, [%0], %1;"
                 :: "r"(mbar), "r"(bytes) : "memory");
}
__device__ __forceinline__ void mbar_arrive(uint32_t mbar) {
    asm volatile("mbarrier.arrive.release.cta.shared.b64 _, [%0];" :: "r"(mbar) : "memory");
}
__device__ __forceinline__ void mbar_wait(uint32_t mbar, uint32_t phase) {
    uint32_t done;
    asm volatile(
        "{\n\t.reg .pred p;\n\t"
        "mbarrier.try_wait.parity.acquire.cta.shared::cta.b64 p, [%1], %2;\n\t"
        "selp.b32 %0, 1, 0, p;\n\t}"
        : "=r"(done) : "r"(mbar), "r"(phase) : "memory");
    if (!done) {
        asm volatile(
            "{\n\t.reg .pred P1;\n\t"
            "W_%=:\n\t"
            "mbarrier.try_wait.parity.acquire.cta.shared::cta.b64 P1, [%0], %1, 0x989680;\n\t"
            "@P1 bra.uni D_%=;\n\t"
            "bra.uni W_%=;\n\t"
            "D_%=:\n\t}"
            :: "r"(mbar), "r"(phase) : "memory");
    }
}
__device__ __forceinline__ void tma_load_2d(uint32_t dst, const CUtensorMap* m,
                                            int cx, int cy, uint32_t mbar) {
    asm volatile(
        "cp.async.bulk.tensor.2d.shared::cta.global.tile.mbarrier::complete_tx::bytes "
        "[%0], [%1, {%2, %3}], [%4];"
        :: "r"(dst), "l"(m), "r"(cx), "r"(cy), "r"(mbar) : "memory");
}
__device__ __forceinline__ void tma_store_2d(const CUtensorMap* m, int cx, int cy,
                                             uint32_t src) {
    asm volatile(
        "cp.async.bulk.tensor.2d.global.shared::cta.tile.bulk_group "
        "[%0, {%1, %2}], [%3];"
        :: "l"(m), "r"(cx), "r"(cy), "r"(src) : "memory");
}
__device__ __forceinline__ void tma_commit() {
    asm volatile("cp.async.bulk.commit_group;" ::: "memory");
}
template <int N>
__device__ __forceinline__ void tma_wait_group() {
    asm volatile("cp.async.bulk.wait_group %0;" :: "n"(N) : "memory");
}
__device__ __forceinline__ void fence_async_shared() {
    asm volatile("fence.proxy.async.shared::cta;" ::: "memory");
}

// ---------------- kernel ----------------
__global__ __launch_bounds__(160, 2)
void ewrls_ws_kernel(const __grid_constant__ CUtensorMap tmx,
                     const __grid_constant__ CUtensorMap tmy,
                     const float* __restrict__ logit_lambda) {
    extern __shared__ char smem[];
    float* xs = (float*)smem;                                  // [XSTG][TT][CT]
    float* ys = (float*)(smem + XSTG * STG_BYTES);             // [YSTG][TT][CT]
    uint64_t* bars = (uint64_t*)(smem + (XSTG + YSTG) * STG_BYTES);

    const int tid   = threadIdx.x;
    const int b     = blockIdx.x >> 2;
    const int ctile = blockIdx.x & 3;
    const int cx    = ctile * CT;
    const int cy0   = b * T_DIM;

    const uint32_t mb  = smem_u32(bars);
    const uint32_t xs0 = smem_u32(xs);
    const uint32_t ys0 = smem_u32(ys);

    auto XFULL  = [&](int i) { return mb + i * 8; };
    auto XEMPTY = [&](int i) { return mb + (XSTG + i) * 8; };
    auto YREADY = [&](int i) { return mb + (2 * XSTG + i) * 8; };
    auto YFREE  = [&](int i) { return mb + (2 * XSTG + YSTG + i) * 8; };

    if (tid == 0) {
#pragma unroll
        for (int i = 0; i < XSTG; i++) { mbar_init(XFULL(i), 1); mbar_init(XEMPTY(i), NCW); }
#pragma unroll
        for (int i = 0; i < YSTG; i++) { mbar_init(YREADY(i), NCW); mbar_init(YFREE(i), 1); }
    }
    __syncthreads();   // only block-wide barrier in the kernel

    if (tid >= CT) {
        // ---------------- producer (single thread of warp 4) ----------------
        if (tid != CT) return;   // lanes 1..31 of producer warp retire

        // prologue: XSTG loads in flight
#pragma unroll
        for (int s = 0; s < XSTG; s++) {
            mbar_expect_tx(XFULL(s), STG_BYTES);
            tma_load_2d(xs0 + s * STG_BYTES, &tmx, cx, cy0 + s * TT, XFULL(s));
        }

#pragma unroll 1
        for (int s = 0; s < NSTG; s++) {
            const int yb = s % YSTG, yr = s / YSTG;
            // consumers finished writing ys[yb] for stage s
            mbar_wait(YREADY(yb), (uint32_t)(yr & 1));
            fence_async_shared();          // generic STS -> async proxy visibility
            tma_store_2d(&tmy, cx, cy0 + s * TT, ys0 + yb * STG_BYTES);
            tma_commit();
            tma_wait_group<YSTG - 1>();    // store s-(YSTG-1) retired
            if (s >= YSTG - 1)
                mbar_arrive(YFREE((s - (YSTG - 1)) % YSTG));

            // refill x ring: load for stage s+XSTG reuses buffer s%XSTG
            if (s + XSTG < NSTG) {
                const int xb = s % XSTG, xr = s / XSTG;
                mbar_wait(XEMPTY(xb), (uint32_t)(xr & 1));
                mbar_expect_tx(XFULL(xb), STG_BYTES);
                tma_load_2d(xs0 + xb * STG_BYTES, &tmx,
                            cx, cy0 + (s + XSTG) * TT, XFULL(xb));
            }
        }
        tma_wait_group<0>();
        return;
    }

    // ---------------- consumers (tid 0..127) ----------------
    const int lane = tid & 31;
    const int c = ctile * CT + tid;
    float l   = __ldg(&logit_lambda[c]);
    float lam = 1.0f / (1.0f + __expf(-l));
    lam = fminf(fmaxf(lam, 1e-4f), 1.0f - 1e-4f);

    float S = 0.0f, Q = 0.0f;

#pragma unroll 1
    for (int s = 0; s < NSTG; s++) {
        const int xb = s % XSTG, xr = s / XSTG;
        const int yb = s % YSTG, yr = s / YSTG;

        mbar_wait(XFULL(xb), (uint32_t)(xr & 1));          // x data landed
        if (s >= YSTG)
            mbar_wait(YFREE(yb), (uint32_t)((yr - 1) & 1)); // ys[yb] store done

        const float* __restrict__ sb = xs + xb * (TT * CT) + tid;
        float*       __restrict__ db = ys + yb * (TT * CT) + tid;
#pragma unroll
        for (int g = 0; g < TT / 8; g++) {
            float xv[8];
#pragma unroll
            for (int u = 0; u < 8; u++) xv[u] = sb[(g * 8 + u) * CT];
#pragma unroll
            for (int u = 0; u < 8; u++) {
                S = fmaf(lam, S, xv[u]);
                Q = fmaf(lam, Q, 1.0f);
                db[(g * 8 + u) * CT] = __fdividef(S, Q);
            }
        }

        // per-warp arrives (count NCW=4): 32x less mbarrier ATOMS traffic
        __syncwarp();
        if (lane == 0) {
            mbar_arrive(XEMPTY(xb));   // done reading xs[xb]
            mbar_arrive(YREADY(yb));   // ys[yb] fully written (release)
        }
    }
}

// ---------------- host ----------------
typedef CUresult (*EncodeTiledFn)(
    CUtensorMap*, CUtensorMapDataType, cuuint32_t, void*,
    const cuuint64_t*, const cuuint64_t*, const cuuint32_t*, const cuuint32_t*,
    CUtensorMapInterleave, CUtensorMapSwizzle, CUtensorMapL2promotion,
    CUtensorMapFloatOOBfill);

static EncodeTiledFn get_encode_fn() {
    static EncodeTiledFn fn = nullptr;
    if (!fn) {
        cudaDriverEntryPointQueryResult qr;
#if CUDART_VERSION >= 12050
        cudaGetDriverEntryPointByVersion("cuTensorMapEncodeTiled", (void**)&fn,
                                         12000, cudaEnableDefault, &qr);
#else
        cudaGetDriverEntryPoint("cuTensorMapEncodeTiled", (void**)&fn,
                                cudaEnableDefault, &qr);
#endif
    }
    return fn;
}

static void make_map(CUtensorMap* m, void* base) {
    cuuint64_t dims[2]    = {C_DIM, (cuuint64_t)B_DIM * T_DIM};
    cuuint64_t strides[1] = {C_DIM * sizeof(float)};
    cuuint32_t box[2]     = {CT, TT};
    cuuint32_t es[2]      = {1, 1};
    get_encode_fn()(m, CU_TENSOR_MAP_DATA_TYPE_FLOAT32, 2, base,
                    dims, strides, box, es,
                    CU_TENSOR_MAP_INTERLEAVE_NONE, CU_TENSOR_MAP_SWIZZLE_NONE,
                    CU_TENSOR_MAP_L2_PROMOTION_L2_128B,
                    CU_TENSOR_MAP_FLOAT_OOB_FILL_NONE);
}

extern "C" void kernel_launch(void* const* d_in, const int* in_sizes, int n_in,
                              void* d_out, int out_size) {
    const float* x;
    const float* logit_lambda;
    if (in_sizes[0] > in_sizes[1]) {
        x = (const float*)d_in[0];
        logit_lambda = (const float*)d_in[1];
    } else {
        x = (const float*)d_in[1];
        logit_lambda = (const float*)d_in[0];
    }
    float* y = (float*)d_out;

    CUtensorMap tmx, tmy;
    make_map(&tmx, (void*)x);
    make_map(&tmy, (void*)y);

    cudaFuncSetAttribute(ewrls_ws_kernel,
                         cudaFuncAttributeMaxDynamicSharedMemorySize, SMEM_BYTES);

    const int blocks = B_DIM * (C_DIM / CT);   // 256
    ewrls_ws_kernel<<<blocks, 160, SMEM_BYTES>>>(tmx, tmy, logit_lambda);
}